// round 3
// baseline (speedup 1.0000x reference)
#include <cuda_runtime.h>
#include <math.h>

#define VSZ 128
#define HW  (VSZ*VSZ)          // 16384
#define NB  4
#define NP  32
#define PE  16
#define EPSF  1e-8f
#define BIGF  3.4e38f

// ---------------- scratch (static device globals; no allocation) ------------
// per edge: A = {v0x, v0y, v1y, ex}; Bv = {ey, ex*inv, ey*inv, ex/(ey+eps)}
// polys compacted: active polys in slots [0,nact), sentinels after.
__device__ float4 g_edges[NB*NP*PE*2];      // 64 KB
__device__ int    g_nact[NB];
__device__ int    g_hv[NB];

// ---------------- kernel A: warp-per-polygon setup + compaction -------------
__global__ __launch_bounds__(1024) void setup_kernel(
    const float* __restrict__ polygons,
    const float* __restrict__ attributes,
    const float* __restrict__ validity)
{
    __shared__ float2 shv[NP][PE];
    __shared__ int    s_act[NP];

    int w = threadIdx.x >> 5;     // poly index within batch (0..31)
    int l = threadIdx.x & 31;
    int b = blockIdx.x;           // batch
    int poly = b * NP + w;

    const float* pp = polygons + (size_t)poly * PE * 2;
    float x = 0.0f, y = 0.0f;
    bool valid = false;
    if (l < PE) {
        x = pp[2*l + 0];
        y = pp[2*l + 1];
        valid = (x + y) != 0.0f;
    }
    unsigned vm = __ballot_sync(0xffffffffu, valid);
    int K   = __popc(vm);
    int pos = __popc(vm & ((1u << l) - 1u));
    if (valid) shv[w][pos] = make_float2(x, y);

    bool act = (K >= 3) && (validity[poly] >= 0.5f);
    if (l == 0) s_act[w] = act ? 1 : 0;
    __syncthreads();

    // per-warp slot via ballot over per-poly flags (lane l holds poly l's flag)
    int flag = s_act[l];
    unsigned am = __ballot_sync(0xffffffffu, flag != 0);
    int nact  = __popc(am);
    int below = __popc(am & ((1u << w) - 1u));   // active polys before w
    int slot  = act ? below : (nact + (w - below));

    if (l < PE) {
        float4 A, Bv;
        if (act && l < K) {
            float2 v0 = shv[w][l];
            float2 v1 = shv[w][(l + 1 == K) ? 0 : l + 1];
            float ex = v1.x - v0.x;
            float ey = v1.y - v0.y;
            float inv = 1.0f / (ex*ex + ey*ey + EPSF);
            A  = make_float4(v0.x, v0.y, v1.y, ex);
            Bv = make_float4(ey, ex*inv, ey*inv, ex / (ey + EPSF));
        } else {
            // sentinel: yc always false, distance -> inf
            A  = make_float4(0.0f, 1e30f, 1e30f, 0.0f);
            Bv = make_float4(0.0f, 0.0f, 0.0f, 0.0f);
        }
        size_t eidx = ((size_t)(b * NP + slot) * PE + l) * 2;
        g_edges[eidx + 0] = A;
        g_edges[eidx + 1] = Bv;
    }

    if (threadIdx.x == 0) {
        g_nact[b] = nact;
        float av = attributes[b];                  // (B,1)
        av = fminf(fmaxf(av, 0.0f), 1.0f);
        int hv = (int)rintf(av * (float)VSZ);      // round-half-even like jnp.rint
        g_hv[b] = min(max(hv, 1), VSZ);
    }
}

// one edge for 2 adjacent pixels; updates min-d2 and crossing parity
#define EDGE_STEP(Eptr, e, m2a, m2b, ca, cb)                            \
    {                                                                   \
        float4 A  = (Eptr)[2*(e) + 0];                                  \
        float4 Bv = (Eptr)[2*(e) + 1];                                  \
        float vy    = py - A.y;                                         \
        bool  yc    = (A.y <= py) != (A.z <= py);                       \
        float ix    = fmaf(Bv.w, vy, A.x);                              \
        float vyeyi = vy * Bv.z;                                        \
        float vx0   = px0 - A.x;                                        \
        float vx1   = vx0 + hstep;                                      \
        float t0 = __saturatef(fmaf(vx0, Bv.y, vyeyi));                 \
        float t1 = __saturatef(fmaf(vx1, Bv.y, vyeyi));                 \
        float dx0 = fmaf(-t0, A.w, vx0);                                \
        float dy0 = fmaf(-t0, Bv.x, vy);                                \
        float dx1 = fmaf(-t1, A.w, vx1);                                \
        float dy1 = fmaf(-t1, Bv.x, vy);                                \
        m2a = fminf(m2a, fmaf(dy0, dy0, dx0*dx0));                      \
        m2b = fminf(m2b, fmaf(dy1, dy1, dx1*dx1));                      \
        ca ^= (yc && (ix > px0));                                       \
        cb ^= (yc && (ix > px1));                                       \
    }

#define MERGE(c, m2, bI, bD2)                                           \
    {                                                                   \
        bool better = (c != bI) ? c : (c ? (m2 > bD2) : (m2 < bD2));    \
        if (better) { bI = c; bD2 = m2; }                               \
    }

// ------- kernel B: fused SDF + soft mask (via min-sdf) + depth broadcast ----
// 128 blocks (one wave), 256 threads, 2 pixels/thread, 2 polys interleaved.
__global__ __launch_bounds__(256) void fused_kernel(float* __restrict__ out)
{
    __shared__ float4 sh[NP*PE*2];   // 16 KB
    __shared__ int    s_nh, s_hv;

    int b    = blockIdx.x >> 5;      // 32 tiles per batch
    int tile = blockIdx.x & 31;
    int t    = threadIdx.x;

    const float4* ge = g_edges + (size_t)b * NP * PE * 2;
    #pragma unroll
    for (int i = 0; i < 4; i++)
        sh[t + 256*i] = ge[t + 256*i];
    if (t == 0) {
        s_nh = (g_nact[b] + 1) >> 1;
        s_hv = g_hv[b];
    }
    __syncthreads();

    int m0 = tile * 512 + t * 2;                 // two adjacent pixels, same row
    const float hstep = 1.0f / (float)(VSZ - 1);
    float px0 = (float)(m0 & (VSZ-1)) * hstep;
    float px1 = px0 + hstep;
    float py  = (float)(m0 >> 7) * hstep;

    float bD2a = BIGF, bD2b = BIGF;
    bool  bIa  = false, bIb  = false;

    int nh = s_nh;
    for (int i = 0; i < nh; i++) {
        const float4* E0 = sh + (size_t)i        * (PE*2);
        const float4* E1 = sh + (size_t)(i + nh) * (PE*2);
        float mP0 = BIGF, mP1 = BIGF, mQ0 = BIGF, mQ1 = BIGF;
        bool  cP0 = false, cP1 = false, cQ0 = false, cQ1 = false;
        #pragma unroll
        for (int e = 0; e < PE; e++) {
            EDGE_STEP(E0, e, mP0, mP1, cP0, cP1);
            EDGE_STEP(E1, e, mQ0, mQ1, cQ0, cQ1);
        }
        MERGE(cP0, mP0, bIa, bD2a);
        MERGE(cP1, mP1, bIb, bD2b);
        MERGE(cQ0, mQ0, bIa, bD2a);
        MERGE(cQ1, mQ1, bIb, bD2b);
    }

    // sigmoid(-100*sdf) of the min signed sdf == max of per-poly masks
    float da = sqrtf(bD2a);
    float db = sqrtf(bD2b);
    float sa = bIa ? -da : da;
    float sb = bIb ? -db : db;
    float va = __fdividef(1.0f, 1.0f + __expf(100.0f * sa));
    float vb = __fdividef(1.0f, 1.0f + __expf(100.0f * sb));

    float2 cv = make_float2(va, vb);
    float2 zv = make_float2(0.0f, 0.0f);
    char* basep = (char*)out + ((size_t)b * VSZ * HW + (size_t)m0) * sizeof(float);
    int hv = s_hv;
    int d = 0;
    #pragma unroll 4
    for (; d < hv; d++)
        *(float2*)(basep + (size_t)d * HW * sizeof(float)) = cv;
    #pragma unroll 4
    for (; d < VSZ; d++)
        *(float2*)(basep + (size_t)d * HW * sizeof(float)) = zv;
}

// ---------------- launch ----------------------------------------------------
extern "C" void kernel_launch(void* const* d_in, const int* in_sizes, int n_in,
                              void* d_out, int out_size)
{
    const float* polygons   = (const float*)d_in[0];   // (4,32,16,2)
    const float* attributes = (const float*)d_in[1];   // (4,1)
    const float* validity   = (const float*)d_in[2];   // (4,32)
    float* out = (float*)d_out;                        // (4,128,128,128)

    setup_kernel<<<NB, 1024>>>(polygons, attributes, validity);
    fused_kernel<<<NB*32, 256>>>(out);
}

// round 4
// speedup vs baseline: 1.0958x; 1.0958x over previous
#include <cuda_runtime.h>
#include <math.h>

#define VSZ 128
#define HW  (VSZ*VSZ)          // 16384
#define NB  4
#define NP  32
#define PE  16
#define NE  (NP*PE)            // 512 edges per batch
#define EPSF  1e-8f
#define BIGF  3.4e38f

// ---------------- scratch (static device globals; no allocation) ------------
// per edge: A = {v0x, v0y, v1y, ex}; Bv = {ey, ex*inv, ey*inv, ex/(ey+eps)}
// polys compacted: active polys occupy slots [0,nact), sentinels after.
__device__ float4 g_edges[NB*NE*2];      // 64 KB
__device__ int    g_nact[NB];
__device__ int    g_hv[NB];

// ---------------- kernel A: setup + compaction (4 blocks x 256) -------------
__global__ __launch_bounds__(256) void setup_kernel(
    const float* __restrict__ polygons,
    const float* __restrict__ attributes,
    const float* __restrict__ validity)
{
    __shared__ float2 shv[NP][PE];
    __shared__ int    s_act[NP], s_K[NP], s_slot[NP];

    int w = threadIdx.x >> 5;     // warp 0..7, handles polys 4w..4w+3
    int l = threadIdx.x & 31;
    int b = blockIdx.x;

    #pragma unroll
    for (int i = 0; i < 4; i++) {
        int n = w*4 + i;
        int poly = b*NP + n;
        const float* pp = polygons + (size_t)poly * PE * 2;
        float x = 0.0f, y = 0.0f;
        bool valid = false;
        if (l < PE) {
            x = pp[2*l + 0];
            y = pp[2*l + 1];
            valid = (x + y) != 0.0f;
        }
        unsigned vm = __ballot_sync(0xffffffffu, valid);
        int K   = __popc(vm);
        int pos = __popc(vm & ((1u << l) - 1u));
        if (valid) shv[n][pos] = make_float2(x, y);
        if (l == 0) {
            s_K[n]   = K;
            s_act[n] = (K >= 3 && validity[poly] >= 0.5f) ? 1 : 0;
        }
    }
    __syncthreads();

    if (w == 0) {   // warp 0: compaction slots via ballot over 32 poly flags
        int flag = s_act[l];
        unsigned am = __ballot_sync(0xffffffffu, flag != 0);
        int nact  = __popc(am);
        int below = __popc(am & ((1u << l) - 1u));
        s_slot[l] = flag ? below : (nact + (l - below));
        if (l == 0) {
            g_nact[b] = nact;
            float av = attributes[b];                  // (B,1)
            av = fminf(fmaxf(av, 0.0f), 1.0f);
            int hv = (int)rintf(av * (float)VSZ);      // half-even, like jnp.rint
            g_hv[b] = min(max(hv, 1), VSZ);
        }
    }
    __syncthreads();

    #pragma unroll
    for (int i = 0; i < 4; i++) {
        int n = w*4 + i;
        int slot = s_slot[n];
        int K    = s_K[n];
        bool act = s_act[n] != 0;
        if (l < PE) {
            float4 A, Bv;
            if (act && l < K) {
                float2 v0 = shv[n][l];
                float2 v1 = shv[n][(l + 1 == K) ? 0 : l + 1];
                float ex = v1.x - v0.x;
                float ey = v1.y - v0.y;
                float inv = 1.0f / (ex*ex + ey*ey + EPSF);
                A  = make_float4(v0.x, v0.y, v1.y, ex);
                Bv = make_float4(ey, ex*inv, ey*inv, ex / (ey + EPSF));
            } else {
                A  = make_float4(0.0f, 1e30f, 1e30f, 0.0f);   // sentinel
                Bv = make_float4(0.0f, 0.0f, 0.0f, 0.0f);
            }
            size_t eidx = ((size_t)(b*NP + slot) * PE + l) * 2;
            g_edges[eidx + 0] = A;
            g_edges[eidx + 1] = Bv;
        }
    }
}

// ------- kernel B: fused SDF + mask + depth broadcast (128 x 512) -----------
// Block covers 4 rows (512 pixels) of one batch. Row-dependent edge terms are
// precomputed once per (row, edge) into smem; inner loop is ~8 fp ops/edge.
__global__ __launch_bounds__(512) void fused_kernel(float* __restrict__ out)
{
    __shared__ float4 sRE[4*NE];      // {c1, ix_enc, vy, v0x} per (row, edge) 32KB
    __shared__ float4 sEC[NE];        // {ex, ey, ex*inv, 0} per edge            8KB
    __shared__ float  s_cmb[512];     // combined mask values                    2KB
    __shared__ int    s_nact, s_hv;

    int b    = blockIdx.x >> 5;       // 32 tiles per batch
    int tile = blockIdx.x & 31;
    int t    = threadIdx.x;

    const float hstep = 1.0f / (float)(VSZ - 1);
    const float4* ge = g_edges + (size_t)b * NE * 2;

    // ---- precompute row-edge table (2048 entries, 4 per thread) ----
    #pragma unroll
    for (int k = 0; k < 4; k++) {
        int i    = t + 512*k;
        int rr   = i >> 9;            // row within block
        int eidx = i & (NE - 1);
        float4 A  = ge[eidx*2 + 0];   // v0x, v0y, v1y, ex
        float4 Bv = ge[eidx*2 + 1];   // ey, ex*inv, ey*inv, ex/(ey+eps)
        float py  = (float)(tile*4 + rr) * hstep;
        float vy  = py - A.y;
        bool  yc  = (A.y <= py) != (A.z <= py);
        float ix  = fmaf(Bv.w, vy, A.x);
        float c1  = fmaf(-A.x, Bv.y, vy * Bv.z);   // t = px*(ex*inv) + c1
        sRE[i] = make_float4(c1, yc ? ix : -BIGF, vy, A.x);
        if (k == 0)                    // rr==0 here; also fill edge constants
            sEC[eidx] = make_float4(A.w, Bv.x, Bv.y, 0.0f);
    }
    if (t == 0) { s_nact = g_nact[b]; s_hv = g_hv[b]; }
    __syncthreads();

    int   rr = t >> 7;
    float px = (float)(t & (VSZ-1)) * hstep;
    const float4* REr = sRE + rr * NE;

    // min over polys of signed d^2 (monotone map of signed distance)
    float S = BIGF;
    int nact = s_nact;
    for (int n = 0; n < nact; n++) {
        const float4* Rp = REr + n*PE;
        const float4* Ep = sEC + n*PE;
        float m2 = BIGF;
        unsigned cnt = 0u;
        #pragma unroll
        for (int e = 0; e < PE; e++) {
            float4 R = Rp[e];          // c1, ix_enc, vy, v0x (warp-broadcast LDS)
            float4 E = Ep[e];          // ex, ey, ex*inv
            float tt = __saturatef(fmaf(px, E.z, R.x));
            float wx = fmaf(tt, E.x, R.w);           // v0x + t*ex
            float dx = px - wx;
            float dy = fmaf(-tt, E.y, R.z);          // vy - t*ey
            float d2 = fmaf(dy, dy, dx*dx);
            m2 = fminf(m2, d2);
            cnt ^= (R.y > px) ? 1u : 0u;             // crossing (yc folded in)
        }
        float s = cnt ? -m2 : m2;
        S = fminf(S, s);
    }

    float d   = sqrtf(fabsf(S));
    float sdf = (S < 0.0f) ? -d : d;
    float v   = __fdividef(1.0f, 1.0f + __expf(100.0f * sdf));

    // ---- stage + depth broadcast with float4 stores ----
    s_cmb[t] = v;
    __syncthreads();

    int chunk = t & 127;               // float4 chunk within the 512-px tile
    int d0    = t >> 7;                // starting depth (0..3), step 4
    float4 val = reinterpret_cast<const float4*>(s_cmb)[chunk];
    float4 z   = make_float4(0.0f, 0.0f, 0.0f, 0.0f);
    int hv  = s_hv;
    int non = (hv - d0 + 3) >> 2;      // # of depths (d0+4i) < hv; in [0,32]
    float* base = out + ((size_t)b * VSZ + d0) * HW + tile*512 + chunk*4;
    int i = 0;
    for (; i < non; i++)
        *reinterpret_cast<float4*>(base + (size_t)i * 4 * HW) = val;
    for (; i < 32; i++)
        *reinterpret_cast<float4*>(base + (size_t)i * 4 * HW) = z;
}

// ---------------- launch ----------------------------------------------------
extern "C" void kernel_launch(void* const* d_in, const int* in_sizes, int n_in,
                              void* d_out, int out_size)
{
    const float* polygons   = (const float*)d_in[0];   // (4,32,16,2)
    const float* attributes = (const float*)d_in[1];   // (4,1)
    const float* validity   = (const float*)d_in[2];   // (4,32)
    float* out = (float*)d_out;                        // (4,128,128,128)

    setup_kernel<<<NB, 256>>>(polygons, attributes, validity);
    fused_kernel<<<NB*32, 512>>>(out);
}

// round 6
// speedup vs baseline: 1.0974x; 1.0014x over previous
#include <cuda_runtime.h>
#include <cstdint>
#include <math.h>

#define VSZ 128
#define HW  (VSZ*VSZ)          // 16384
#define NB  4
#define NP  32
#define PE  16
#define NE  (NP*PE)            // 512 edges per batch
#define EPSF  1e-8f
#define BIGF  3.4e38f

// ---------------- scratch (static device globals; no allocation) ------------
// per edge: A = {v0x, v0y, v1y, ex}; Bv = {ey, ex*inv, ey*inv, ex/(ey+eps)}
// polys compacted: active polys occupy slots [0,nact), sentinels after.
__device__ float4 g_edges[NB*NE*2];      // 64 KB
__device__ int    g_nact[NB];
__device__ int    g_hv[NB];

// ---------------- kernel A: setup + compaction (4 blocks x 256) -------------
__global__ __launch_bounds__(256) void setup_kernel(
    const float* __restrict__ polygons,
    const float* __restrict__ attributes,
    const float* __restrict__ validity)
{
    __shared__ float2 shv[NP][PE];
    __shared__ int    s_act[NP], s_K[NP], s_slot[NP];

    int w = threadIdx.x >> 5;     // warp 0..7, handles polys 4w..4w+3
    int l = threadIdx.x & 31;
    int b = blockIdx.x;

    #pragma unroll
    for (int i = 0; i < 4; i++) {
        int n = w*4 + i;
        int poly = b*NP + n;
        const float* pp = polygons + (size_t)poly * PE * 2;
        float x = 0.0f, y = 0.0f;
        bool valid = false;
        if (l < PE) {
            x = pp[2*l + 0];
            y = pp[2*l + 1];
            valid = (x + y) != 0.0f;
        }
        unsigned vm = __ballot_sync(0xffffffffu, valid);
        int K   = __popc(vm);
        int pos = __popc(vm & ((1u << l) - 1u));
        if (valid) shv[n][pos] = make_float2(x, y);
        if (l == 0) {
            s_K[n]   = K;
            s_act[n] = (K >= 3 && validity[poly] >= 0.5f) ? 1 : 0;
        }
    }
    __syncthreads();

    if (w == 0) {   // warp 0: compaction slots via ballot over 32 poly flags
        int flag = s_act[l];
        unsigned am = __ballot_sync(0xffffffffu, flag != 0);
        int nact  = __popc(am);
        int below = __popc(am & ((1u << l) - 1u));
        s_slot[l] = flag ? below : (nact + (l - below));
        if (l == 0) {
            g_nact[b] = nact;
            float av = attributes[b];                  // (B,1)
            av = fminf(fmaxf(av, 0.0f), 1.0f);
            int hv = (int)rintf(av * (float)VSZ);      // half-even, like jnp.rint
            g_hv[b] = min(max(hv, 1), VSZ);
        }
    }
    __syncthreads();

    #pragma unroll
    for (int i = 0; i < 4; i++) {
        int n = w*4 + i;
        int slot = s_slot[n];
        int K    = s_K[n];
        bool act = s_act[n] != 0;
        if (l < PE) {
            float4 A, Bv;
            if (act && l < K) {
                float2 v0 = shv[n][l];
                float2 v1 = shv[n][(l + 1 == K) ? 0 : l + 1];
                float ex = v1.x - v0.x;
                float ey = v1.y - v0.y;
                float inv = 1.0f / (ex*ex + ey*ey + EPSF);
                A  = make_float4(v0.x, v0.y, v1.y, ex);
                Bv = make_float4(ey, ex*inv, ey*inv, ex / (ey + EPSF));
            } else {
                A  = make_float4(0.0f, 1e30f, 1e30f, 0.0f);   // sentinel
                Bv = make_float4(0.0f, 0.0f, 0.0f, 0.0f);
            }
            size_t eidx = ((size_t)(b*NP + slot) * PE + l) * 2;
            g_edges[eidx + 0] = A;
            g_edges[eidx + 1] = Bv;
        }
    }
}

// ------- kernel B: fused SDF + mask + depth broadcast (128 x 512) -----------
// Block covers 4 rows (512 px) of one batch. Row-dependent edge terms are
// hoisted per (row, edge) into smem; early-exit when a warp's mask saturates;
// depth broadcast done with cp.async.bulk (2KB per depth slice).
__global__ __launch_bounds__(512) void fused_kernel(float* __restrict__ out)
{
    __shared__ float4 sRE[4*NE];                   // {c1, ix_enc, vy, v0x}  32KB
    __shared__ float4 sEC[NE];                     // {ex, ey, ex*inv, 0}     8KB
    __shared__ __align__(16) float s_cmb[512];     // combined tile           2KB
    __shared__ __align__(16) float s_zero[512];    // zero tile               2KB
    __shared__ int    s_nact, s_hv;

    int b    = blockIdx.x >> 5;       // 32 tiles per batch
    int tile = blockIdx.x & 31;
    int t    = threadIdx.x;

    const float hstep = 1.0f / (float)(VSZ - 1);
    const float4* ge = g_edges + (size_t)b * NE * 2;

    // ---- precompute row-edge table (2048 entries, 4 per thread) ----
    #pragma unroll
    for (int k = 0; k < 4; k++) {
        int i    = t + 512*k;
        int rr   = i >> 9;            // row within block
        int eidx = i & (NE - 1);
        float4 A  = ge[eidx*2 + 0];   // v0x, v0y, v1y, ex
        float4 Bv = ge[eidx*2 + 1];   // ey, ex*inv, ey*inv, ex/(ey+eps)
        float py  = (float)(tile*4 + rr) * hstep;
        float vy  = py - A.y;
        bool  yc  = (A.y <= py) != (A.z <= py);
        float ix  = fmaf(Bv.w, vy, A.x);
        float c1  = fmaf(-A.x, Bv.y, vy * Bv.z);   // t = px*(ex*inv) + c1
        sRE[i] = make_float4(c1, yc ? ix : -BIGF, vy, A.x);
        if (k == 0)                    // rr==0 here; also fill edge constants
            sEC[eidx] = make_float4(A.w, Bv.x, Bv.y, 0.0f);
    }
    s_zero[t] = 0.0f;
    if (t == 0) { s_nact = g_nact[b]; s_hv = g_hv[b]; }
    __syncthreads();

    int   rr = t >> 7;
    float px = (float)(t & (VSZ-1)) * hstep;
    const float4* REr = sRE + rr * NE;

    // min over polys of signed d^2 (monotone map of signed distance)
    float S = BIGF;
    int nact = s_nact;
    for (int n = 0; n < nact; n++) {
        const float4* Rp = REr + n*PE;
        const float4* Ep = sEC + n*PE;
        float m2 = BIGF;
        unsigned cnt = 0u;
        #pragma unroll
        for (int e = 0; e < PE; e++) {
            float4 R = Rp[e];          // c1, ix_enc, vy, v0x (warp-broadcast LDS)
            float4 E = Ep[e];          // ex, ey, ex*inv
            float tt = __saturatef(fmaf(px, E.z, R.x));
            float wx = fmaf(tt, E.x, R.w);           // v0x + t*ex
            float dx = px - wx;
            float dy = fmaf(-tt, E.y, R.z);          // vy - t*ey
            float d2 = fmaf(dy, dy, dx*dx);
            m2 = fminf(m2, d2);
            cnt ^= (R.y > px) ? 1u : 0u;             // crossing (yc folded in)
        }
        float s = cnt ? -m2 : m2;
        S = fminf(S, s);
        // warp-coherent saturation exit: sdf < -0.1 for all lanes -> mask
        // within 4.5e-5 of 1 and can only increase; 1e-3 tol -> safe to stop.
        if (__all_sync(0xffffffffu, S < -0.01f)) break;
    }

    float d   = sqrtf(fabsf(S));
    float sdf = (S < 0.0f) ? -d : d;
    float v   = __fdividef(1.0f, 1.0f + __expf(100.0f * sdf));

    // ---- stage tile, then depth-broadcast with async bulk copies ----
    s_cmb[t] = v;
    __syncthreads();

    if (t < VSZ) {
        // publish generic smem writes to the async proxy
        asm volatile("fence.proxy.async.shared::cta;" ::: "memory");
        int dz = t;                                  // depth slice
        const float* srcp = (dz < s_hv) ? s_cmb : s_zero;
        unsigned int saddr;
        asm("{ .reg .u64 a; cvta.to.shared.u64 a, %1; cvt.u32.u64 %0, a; }"
            : "=r"(saddr) : "l"(srcp));
        float* gdst = out + ((size_t)b * VSZ + dz) * HW + tile * 512;
        asm volatile("cp.async.bulk.global.shared::cta.bulk_group [%0], [%1], %2;"
                     :: "l"(gdst), "r"(saddr), "r"(512u * 4u) : "memory");
        asm volatile("cp.async.bulk.commit_group;" ::: "memory");
        asm volatile("cp.async.bulk.wait_group 0;" ::: "memory");
    }
}

// ---------------- launch ----------------------------------------------------
extern "C" void kernel_launch(void* const* d_in, const int* in_sizes, int n_in,
                              void* d_out, int out_size)
{
    const float* polygons   = (const float*)d_in[0];   // (4,32,16,2)
    const float* attributes = (const float*)d_in[1];   // (4,1)
    const float* validity   = (const float*)d_in[2];   // (4,32)
    float* out = (float*)d_out;                        // (4,128,128,128)

    setup_kernel<<<NB, 256>>>(polygons, attributes, validity);
    fused_kernel<<<NB*32, 512>>>(out);
}